// round 1
// baseline (speedup 1.0000x reference)
#include <cuda_runtime.h>

#define NN 100000
#define EE 1600000
#define GG 64
#define HID 64
#define EDIM 16
#define OUTD 128

// ---------------- scratch (device globals; no allocation) ----------------
__device__ float d_cnt[NN];            // incoming-edge counts
__device__ float d_loop[NN * EDIM];    // self-loop attrs (mean of incoming)
__device__ float d_xl[NN * HID];       // source transform
__device__ float d_xr[NN * HID];       // target transform
__device__ float d_acc[NN * HID];      // sum_e z * xl[src]
__device__ float d_den[NN * 4];        // sum_e z per head
__device__ float d_x[NN * HID];        // layer output
__device__ float d_g[GG * HID];        // pooled sums
__device__ float d_gc[GG];             // pooled counts

__device__ __forceinline__ void red4(float* p, float a, float b, float c, float d) {
    asm volatile("red.global.add.v4.f32 [%0], {%1,%2,%3,%4};"
                 :: "l"(p), "f"(a), "f"(b), "f"(c), "f"(d) : "memory");
}

// ---------------- self-loop mean edge attr ----------------
__global__ void loop_accum_k(const int* __restrict__ ei, const float* __restrict__ ea) {
    int e = blockIdx.x * blockDim.x + threadIdx.x;
    if (e >= EE) return;
    int dst = ei[EE + e];
    const float4* a4 = reinterpret_cast<const float4*>(ea + (size_t)e * EDIM);
    float* o = d_loop + (size_t)dst * EDIM;
#pragma unroll
    for (int i = 0; i < 4; i++) {
        float4 v = a4[i];
        red4(o + 4 * i, v.x, v.y, v.z, v.w);
    }
    atomicAdd(&d_cnt[dst], 1.0f);
}

__global__ void loop_norm_k() {
    int t = blockIdx.x * blockDim.x + threadIdx.x;
    if (t >= NN * EDIM) return;
    float c = d_cnt[t / EDIM];
    d_loop[t] = d_loop[t] / fmaxf(c, 1.0f);
}

// ---------------- node projections: xl = x@Wl+bl, xr = x@Wr+br ----------------
__global__ void node_proj_k(const float* __restrict__ x,
                            const float* __restrict__ Wl, const float* __restrict__ bl,
                            const float* __restrict__ Wr, const float* __restrict__ br) {
    __shared__ float sWl[64 * 64];
    __shared__ float sWr[64 * 64];
    __shared__ float sx[4 * 64];
    for (int i = threadIdx.x; i < 64 * 64; i += blockDim.x) {
        sWl[i] = Wl[i];
        sWr[i] = Wr[i];
    }
    __syncthreads();
    int rl = threadIdx.x >> 6;   // 0..3 row-in-tile
    int c  = threadIdx.x & 63;   // output column
    float blc = bl[c], brc = br[c];
    for (int base = blockIdx.x * 4; base < NN; base += gridDim.x * 4) {
        __syncthreads();
        int r = base + rl;
        if (r < NN) sx[threadIdx.x] = x[(size_t)r * 64 + c];
        __syncthreads();
        if (r < NN) {
            float sl = blc, sr = brc;
#pragma unroll
            for (int k = 0; k < 64; k++) {
                float xv = sx[rl * 64 + k];
                sl += xv * sWl[k * 64 + c];
                sr += xv * sWr[k * 64 + c];
            }
            d_xl[(size_t)r * 64 + c] = sl;
            d_xr[(size_t)r * 64 + c] = sr;
        }
    }
}

// ---------------- fused edge pass: score -> exp -> atomic accumulate ----------------
// One warp per edge (E real edges + N self-loops).
// Lane l owns channels {2l, 2l+1}; head = lane>>3 (8 lanes per head of 16 channels).
__global__ void edge_pass_k(const int* __restrict__ ei, const float* __restrict__ ea,
                            const float* __restrict__ We, const float* __restrict__ att) {
    __shared__ float sWe[EDIM * 64];
    __shared__ float sAtt[64];
    for (int i = threadIdx.x; i < EDIM * 64; i += blockDim.x) sWe[i] = We[i];
    if (threadIdx.x < 64) sAtt[threadIdx.x] = att[threadIdx.x];
    __syncthreads();

    const unsigned F = 0xffffffffu;
    int lane = threadIdx.x & 31;
    int wid = (blockIdx.x * blockDim.x + threadIdx.x) >> 5;
    int nwarp = (gridDim.x * blockDim.x) >> 5;
    const float2* xl2p = reinterpret_cast<const float2*>(d_xl);
    const float2* xr2p = reinterpret_cast<const float2*>(d_xr);
    const float2* at2p = reinterpret_cast<const float2*>(sAtt);
    const float2* we2p = reinterpret_cast<const float2*>(sWe);

    for (int e = wid; e < EE + NN; e += nwarp) {
        int src, dst;
        const float* eap;
        if (e < EE) {
            src = ei[e];
            dst = ei[EE + e];
            eap = ea + (size_t)e * EDIM;
        } else {
            src = dst = e - EE;
            eap = d_loop + (size_t)(e - EE) * EDIM;
        }
        float eav = (lane < EDIM) ? eap[lane] : 0.0f;

        // eproj for this lane's two channels
        float epx = 0.0f, epy = 0.0f;
#pragma unroll
        for (int k = 0; k < EDIM; k++) {
            float a = __shfl_sync(F, eav, k);
            float2 w = we2p[k * 32 + lane];
            epx += a * w.x;
            epy += a * w.y;
        }
        float2 xl2 = xl2p[(size_t)src * 32 + lane];
        float2 xr2 = xr2p[(size_t)dst * 32 + lane];
        float m0 = xl2.x + xr2.x + epx;
        float m1 = xl2.y + xr2.y + epy;
        m0 = (m0 > 0.0f) ? m0 : 0.2f * m0;   // leaky_relu
        m1 = (m1 > 0.0f) ? m1 : 0.2f * m1;
        float2 at = at2p[lane];
        float s = m0 * at.x + m1 * at.y;
        // per-head reduce (8 lanes per head, xor stays within group)
        s += __shfl_xor_sync(F, s, 1);
        s += __shfl_xor_sync(F, s, 2);
        s += __shfl_xor_sync(F, s, 4);
        float z = __expf(s);   // softmax without max-shift (scores O(1); exact ratio)

        float wx = z * xl2.x;
        float wy = z * xl2.y;
        // lane l<16 collects 4 consecutive channels from lanes 2l, 2l+1
        int l2a = (2 * lane) & 31;
        int l2b = (2 * lane + 1) & 31;
        float px = __shfl_sync(F, wx, l2a);
        float py = __shfl_sync(F, wy, l2a);
        float qx = __shfl_sync(F, wx, l2b);
        float qy = __shfl_sync(F, wy, l2b);
        float zh0 = __shfl_sync(F, z, 0);
        float zh1 = __shfl_sync(F, z, 8);
        float zh2 = __shfl_sync(F, z, 16);
        float zh3 = __shfl_sync(F, z, 24);
        if (lane < 16) {
            red4(d_acc + (size_t)dst * 64 + 4 * lane, px, py, qx, qy);
        } else if (lane == 16) {
            red4(d_den + (size_t)dst * 4, zh0, zh1, zh2, zh3);
        }
    }
}

// ---------------- finalize layer: x = relu(acc/den + bias) ----------------
__global__ void node_out_k(const float* __restrict__ bias) {
    int t = blockIdx.x * blockDim.x + threadIdx.x;
    if (t >= NN * HID) return;
    int node = t >> 6;
    int c = t & 63;
    int h = c >> 4;
    float v = d_acc[t] / d_den[node * 4 + h] + bias[c];
    d_x[t] = fmaxf(v, 0.0f);
}

// ---------------- global mean pool ----------------
__global__ void pool_k(const int* __restrict__ batch) {
    int t = blockIdx.x * blockDim.x + threadIdx.x;
    if (t >= NN * 16) return;
    int node = t >> 4;
    int part = t & 15;
    int b = batch[node];
    float4 v = reinterpret_cast<const float4*>(d_x)[(size_t)node * 16 + part];
    red4(d_g + b * 64 + part * 4, v.x, v.y, v.z, v.w);
    if (part == 0) atomicAdd(&d_gc[b], 1.0f);
}

// ---------------- MLP head ----------------
__global__ void mlp_k(const float* __restrict__ W1, const float* __restrict__ b1,
                      const float* __restrict__ W2, const float* __restrict__ b2,
                      float* __restrict__ out) {
    __shared__ float gx[64];
    __shared__ float hh[128];
    int g = blockIdx.x;
    int t = threadIdx.x;
    if (t < 64) gx[t] = d_g[g * 64 + t] / fmaxf(d_gc[g], 1.0f);
    __syncthreads();
    float s = b1[t];
#pragma unroll
    for (int k = 0; k < 64; k++) s += gx[k] * W1[k * 128 + t];
    hh[t] = fmaxf(s, 0.0f);
    __syncthreads();
    float o = b2[t];
#pragma unroll
    for (int k = 0; k < 128; k++) o += hh[k] * W2[k * 128 + t];
    out[g * 128 + t] = o;
}

// ---------------- launch ----------------
extern "C" void kernel_launch(void* const* d_in, const int* in_sizes, int n_in,
                              void* d_out, int out_size) {
    const float* x0     = (const float*)d_in[0];
    const int*   ei     = (const int*)d_in[1];
    const float* ea     = (const float*)d_in[2];
    const int*   batch  = (const int*)d_in[3];
    const float* l0Wl   = (const float*)d_in[4];
    const float* l0bl   = (const float*)d_in[5];
    const float* l0Wr   = (const float*)d_in[6];
    const float* l0br   = (const float*)d_in[7];
    const float* l0We   = (const float*)d_in[8];
    const float* l0att  = (const float*)d_in[9];
    const float* l0bias = (const float*)d_in[10];
    const float* l1Wl   = (const float*)d_in[11];
    const float* l1bl   = (const float*)d_in[12];
    const float* l1Wr   = (const float*)d_in[13];
    const float* l1br   = (const float*)d_in[14];
    const float* l1We   = (const float*)d_in[15];
    const float* l1att  = (const float*)d_in[16];
    const float* l1bias = (const float*)d_in[17];
    const float* W1     = (const float*)d_in[18];
    const float* b1     = (const float*)d_in[19];
    const float* W2     = (const float*)d_in[20];
    const float* b2     = (const float*)d_in[21];
    float* out = (float*)d_out;

    void *pcnt, *ploop, *pacc, *pden, *pg, *pgc, *px;
    cudaGetSymbolAddress(&pcnt, d_cnt);
    cudaGetSymbolAddress(&ploop, d_loop);
    cudaGetSymbolAddress(&pacc, d_acc);
    cudaGetSymbolAddress(&pden, d_den);
    cudaGetSymbolAddress(&pg, d_g);
    cudaGetSymbolAddress(&pgc, d_gc);
    cudaGetSymbolAddress(&px, d_x);
    (void)px;

    cudaMemsetAsync(pcnt, 0, NN * sizeof(float));
    cudaMemsetAsync(ploop, 0, NN * EDIM * sizeof(float));
    cudaMemsetAsync(pg, 0, GG * HID * sizeof(float));
    cudaMemsetAsync(pgc, 0, GG * sizeof(float));

    loop_accum_k<<<(EE + 255) / 256, 256>>>(ei, ea);
    loop_norm_k<<<(NN * EDIM + 255) / 256, 256>>>();

    // ---- layer 0 ----
    node_proj_k<<<2048, 256>>>(x0, l0Wl, l0bl, l0Wr, l0br);
    cudaMemsetAsync(pacc, 0, (size_t)NN * HID * sizeof(float));
    cudaMemsetAsync(pden, 0, (size_t)NN * 4 * sizeof(float));
    edge_pass_k<<<2048, 256>>>(ei, ea, l0We, l0att);
    node_out_k<<<(NN * HID + 255) / 256, 256>>>(l0bias);

    // ---- layer 1 ----
    {
        void* pxx;
        cudaGetSymbolAddress(&pxx, d_x);
        node_proj_k<<<2048, 256>>>((const float*)pxx, l1Wl, l1bl, l1Wr, l1br);
    }
    cudaMemsetAsync(pacc, 0, (size_t)NN * HID * sizeof(float));
    cudaMemsetAsync(pden, 0, (size_t)NN * 4 * sizeof(float));
    edge_pass_k<<<2048, 256>>>(ei, ea, l1We, l1att);
    node_out_k<<<(NN * HID + 255) / 256, 256>>>(l1bias);

    // ---- pool + MLP ----
    pool_k<<<(NN * 16 + 255) / 256, 256>>>(batch);
    mlp_k<<<GG, OUTD>>>(W1, b1, W2, b2, out);
}

// round 2
// speedup vs baseline: 1.1840x; 1.1840x over previous
#include <cuda_runtime.h>

#define NN 100000
#define EE 1600000
#define GG 64
#define HID 64
#define EDIM 16
#define OUTD 128

// ---------------- scratch (device globals; no allocation) ----------------
__device__ float d_cnt[NN];            // incoming-edge counts
__device__ float d_loop[NN * EDIM];    // self-loop attrs (mean of incoming)
__device__ float d_xl[NN * HID];       // source transform
__device__ float d_xr[NN * HID];       // target transform
__device__ float d_acc[NN * HID];      // sum_e z * xl[src]
__device__ float d_den[NN * 4];        // sum_e z per head
__device__ float d_x[NN * HID];        // layer output
__device__ float d_g[GG * HID];        // pooled sums
__device__ float d_gc[GG];             // pooled counts

__device__ __forceinline__ void red4(float* p, float a, float b, float c, float d) {
    asm volatile("red.global.add.v4.f32 [%0], {%1,%2,%3,%4};"
                 :: "l"(p), "f"(a), "f"(b), "f"(c), "f"(d) : "memory");
}
__device__ __forceinline__ void red2(float* p, float a, float b) {
    asm volatile("red.global.add.v2.f32 [%0], {%1,%2};"
                 :: "l"(p), "f"(a), "f"(b) : "memory");
}

// ---------------- self-loop mean edge attr ----------------
__global__ void loop_accum_k(const int* __restrict__ ei, const float* __restrict__ ea) {
    int e = blockIdx.x * blockDim.x + threadIdx.x;
    if (e >= EE) return;
    int dst = ei[EE + e];
    const float4* a4 = reinterpret_cast<const float4*>(ea + (size_t)e * EDIM);
    float* o = d_loop + (size_t)dst * EDIM;
#pragma unroll
    for (int i = 0; i < 4; i++) {
        float4 v = a4[i];
        red4(o + 4 * i, v.x, v.y, v.z, v.w);
    }
    atomicAdd(&d_cnt[dst], 1.0f);
}

__global__ void loop_norm_k() {
    int t = blockIdx.x * blockDim.x + threadIdx.x;
    if (t >= NN * EDIM) return;
    float c = d_cnt[t >> 4];
    d_loop[t] = d_loop[t] / fmaxf(c, 1.0f);
}

// ---------------- node projections: xl = x@Wl+bl, xr = x@Wr+br ----------------
// 16 rows per block-iteration, 4 rows per thread (register blocking to amortize
// weight LDS over 16 FMA instead of 4).
__global__ void node_proj_k(const float* __restrict__ x,
                            const float* __restrict__ Wl, const float* __restrict__ bl,
                            const float* __restrict__ Wr, const float* __restrict__ br) {
    __shared__ float sWl[64 * 64];
    __shared__ float sWr[64 * 64];
    __shared__ float sx[16 * 64];
    for (int i = threadIdx.x; i < 64 * 64; i += blockDim.x) {
        sWl[i] = Wl[i];
        sWr[i] = Wr[i];
    }
    int c  = threadIdx.x & 63;   // output column
    int rl = threadIdx.x >> 6;   // 0..3 -> row group rl*4 .. rl*4+3
    float blc = bl[c], brc = br[c];
    for (int base = blockIdx.x * 16; base < NN; base += gridDim.x * 16) {
        __syncthreads();
        for (int i = threadIdx.x; i < 16 * 64; i += 256) {
            int r = base + (i >> 6);
            sx[i] = (r < NN) ? x[(size_t)r * 64 + (i & 63)] : 0.0f;
        }
        __syncthreads();
        float s0 = blc, s1 = blc, s2 = blc, s3 = blc;
        float t0 = brc, t1 = brc, t2 = brc, t3 = brc;
        const float* xrow = sx + rl * 4 * 64;
#pragma unroll
        for (int k = 0; k < 64; k++) {
            float wl = sWl[k * 64 + c];
            float wr = sWr[k * 64 + c];
            float x0 = xrow[0 * 64 + k];
            float x1 = xrow[1 * 64 + k];
            float x2 = xrow[2 * 64 + k];
            float x3 = xrow[3 * 64 + k];
            s0 += x0 * wl; t0 += x0 * wr;
            s1 += x1 * wl; t1 += x1 * wr;
            s2 += x2 * wl; t2 += x2 * wr;
            s3 += x3 * wl; t3 += x3 * wr;
        }
        int r0 = base + rl * 4;
        if (r0 + 0 < NN) { d_xl[(size_t)(r0 + 0) * 64 + c] = s0; d_xr[(size_t)(r0 + 0) * 64 + c] = t0; }
        if (r0 + 1 < NN) { d_xl[(size_t)(r0 + 1) * 64 + c] = s1; d_xr[(size_t)(r0 + 1) * 64 + c] = t1; }
        if (r0 + 2 < NN) { d_xl[(size_t)(r0 + 2) * 64 + c] = s2; d_xr[(size_t)(r0 + 2) * 64 + c] = t2; }
        if (r0 + 3 < NN) { d_xl[(size_t)(r0 + 3) * 64 + c] = s3; d_xr[(size_t)(r0 + 3) * 64 + c] = t3; }
    }
}

// ---------------- fused edge pass: score -> exp -> atomic accumulate ----------------
// One warp per edge. Lane l owns channels {2l, 2l+1}; head = lane>>3.
// We and att live in REGISTERS (warp-invariant): zero shared-memory traffic in
// the inner loop -> L1tex pipe only carries gathers + atomics.
__global__ void edge_pass_k(const int* __restrict__ ei, const float* __restrict__ ea,
                            const float* __restrict__ We, const float* __restrict__ att) {
    const unsigned F = 0xffffffffu;
    int lane = threadIdx.x & 31;

    // per-lane weight column pair: w[k] = We[k][2*lane .. 2*lane+1]
    float2 w[EDIM];
    const float2* We2 = reinterpret_cast<const float2*>(We);
#pragma unroll
    for (int k = 0; k < EDIM; k++) w[k] = We2[k * 32 + lane];
    float2 at = reinterpret_cast<const float2*>(att)[lane];

    int wid = (blockIdx.x * blockDim.x + threadIdx.x) >> 5;
    int nwarp = (gridDim.x * blockDim.x) >> 5;
    const float2* xl2p = reinterpret_cast<const float2*>(d_xl);
    const float2* xr2p = reinterpret_cast<const float2*>(d_xr);

    for (int e = wid; e < EE + NN; e += nwarp) {
        int src, dst;
        const float* eap;
        if (e < EE) {
            src = ei[e];
            dst = ei[EE + e];
            eap = ea + (size_t)e * EDIM;
        } else {
            src = dst = e - EE;
            eap = d_loop + (size_t)(e - EE) * EDIM;
        }
        float eav = (lane < EDIM) ? eap[lane] : 0.0f;

        float epx = 0.0f, epy = 0.0f;
#pragma unroll
        for (int k = 0; k < EDIM; k++) {
            float a = __shfl_sync(F, eav, k);
            epx += a * w[k].x;
            epy += a * w[k].y;
        }
        float2 xl2 = xl2p[(size_t)src * 32 + lane];
        float2 xr2 = xr2p[(size_t)dst * 32 + lane];
        float m0 = xl2.x + xr2.x + epx;
        float m1 = xl2.y + xr2.y + epy;
        m0 = (m0 > 0.0f) ? m0 : 0.2f * m0;   // leaky_relu
        m1 = (m1 > 0.0f) ? m1 : 0.2f * m1;
        float s = m0 * at.x + m1 * at.y;
        // per-head reduce (8 lanes per head)
        s += __shfl_xor_sync(F, s, 1);
        s += __shfl_xor_sync(F, s, 2);
        s += __shfl_xor_sync(F, s, 4);
        float z = __expf(s);   // softmax without max-shift (scores O(1); exact ratio)

        // all 32 lanes write their own channel pair directly
        red2(d_acc + (size_t)dst * 64 + 2 * lane, z * xl2.x, z * xl2.y);
        if ((lane & 7) == 0)
            atomicAdd(&d_den[(size_t)dst * 4 + (lane >> 3)], z);
    }
}

// ---------------- finalize layer: x = relu(acc/den + bias) ----------------
__global__ void node_out_k(const float* __restrict__ bias) {
    int t = blockIdx.x * blockDim.x + threadIdx.x;
    if (t >= NN * HID) return;
    int node = t >> 6;
    int c = t & 63;
    int h = c >> 4;
    float v = d_acc[t] / d_den[node * 4 + h] + bias[c];
    d_x[t] = fmaxf(v, 0.0f);
}

// ---------------- global mean pool ----------------
__global__ void pool_k(const int* __restrict__ batch) {
    int t = blockIdx.x * blockDim.x + threadIdx.x;
    if (t >= NN * 16) return;
    int node = t >> 4;
    int part = t & 15;
    int b = batch[node];
    float4 v = reinterpret_cast<const float4*>(d_x)[(size_t)node * 16 + part];
    red4(d_g + b * 64 + part * 4, v.x, v.y, v.z, v.w);
    if (part == 0) atomicAdd(&d_gc[b], 1.0f);
}

// ---------------- MLP head ----------------
__global__ void mlp_k(const float* __restrict__ W1, const float* __restrict__ b1,
                      const float* __restrict__ W2, const float* __restrict__ b2,
                      float* __restrict__ out) {
    __shared__ float gx[64];
    __shared__ float hh[128];
    int g = blockIdx.x;
    int t = threadIdx.x;
    if (t < 64) gx[t] = d_g[g * 64 + t] / fmaxf(d_gc[g], 1.0f);
    __syncthreads();
    float s = b1[t];
#pragma unroll
    for (int k = 0; k < 64; k++) s += gx[k] * W1[k * 128 + t];
    hh[t] = fmaxf(s, 0.0f);
    __syncthreads();
    float o = b2[t];
#pragma unroll
    for (int k = 0; k < 128; k++) o += hh[k] * W2[k * 128 + t];
    out[g * 128 + t] = o;
}

// ---------------- launch ----------------
extern "C" void kernel_launch(void* const* d_in, const int* in_sizes, int n_in,
                              void* d_out, int out_size) {
    const float* x0     = (const float*)d_in[0];
    const int*   ei     = (const int*)d_in[1];
    const float* ea     = (const float*)d_in[2];
    const int*   batch  = (const int*)d_in[3];
    const float* l0Wl   = (const float*)d_in[4];
    const float* l0bl   = (const float*)d_in[5];
    const float* l0Wr   = (const float*)d_in[6];
    const float* l0br   = (const float*)d_in[7];
    const float* l0We   = (const float*)d_in[8];
    const float* l0att  = (const float*)d_in[9];
    const float* l0bias = (const float*)d_in[10];
    const float* l1Wl   = (const float*)d_in[11];
    const float* l1bl   = (const float*)d_in[12];
    const float* l1Wr   = (const float*)d_in[13];
    const float* l1br   = (const float*)d_in[14];
    const float* l1We   = (const float*)d_in[15];
    const float* l1att  = (const float*)d_in[16];
    const float* l1bias = (const float*)d_in[17];
    const float* W1     = (const float*)d_in[18];
    const float* b1     = (const float*)d_in[19];
    const float* W2     = (const float*)d_in[20];
    const float* b2     = (const float*)d_in[21];
    float* out = (float*)d_out;

    void *pcnt, *ploop, *pacc, *pden, *pg, *pgc, *px;
    cudaGetSymbolAddress(&pcnt, d_cnt);
    cudaGetSymbolAddress(&ploop, d_loop);
    cudaGetSymbolAddress(&pacc, d_acc);
    cudaGetSymbolAddress(&pden, d_den);
    cudaGetSymbolAddress(&pg, d_g);
    cudaGetSymbolAddress(&pgc, d_gc);
    cudaGetSymbolAddress(&px, d_x);

    cudaMemsetAsync(pcnt, 0, NN * sizeof(float));
    cudaMemsetAsync(ploop, 0, NN * EDIM * sizeof(float));
    cudaMemsetAsync(pg, 0, GG * HID * sizeof(float));
    cudaMemsetAsync(pgc, 0, GG * sizeof(float));

    loop_accum_k<<<(EE + 255) / 256, 256>>>(ei, ea);
    loop_norm_k<<<(NN * EDIM + 255) / 256, 256>>>();

    // ---- layer 0 ----
    node_proj_k<<<2048, 256>>>(x0, l0Wl, l0bl, l0Wr, l0br);
    cudaMemsetAsync(pacc, 0, (size_t)NN * HID * sizeof(float));
    cudaMemsetAsync(pden, 0, (size_t)NN * 4 * sizeof(float));
    edge_pass_k<<<2048, 256>>>(ei, ea, l0We, l0att);
    node_out_k<<<(NN * HID + 255) / 256, 256>>>(l0bias);

    // ---- layer 1 ----
    node_proj_k<<<2048, 256>>>((const float*)px, l1Wl, l1bl, l1Wr, l1br);
    cudaMemsetAsync(pacc, 0, (size_t)NN * HID * sizeof(float));
    cudaMemsetAsync(pden, 0, (size_t)NN * 4 * sizeof(float));
    edge_pass_k<<<2048, 256>>>(ei, ea, l1We, l1att);
    node_out_k<<<(NN * HID + 255) / 256, 256>>>(l1bias);

    // ---- pool + MLP ----
    pool_k<<<(NN * 16 + 255) / 256, 256>>>(batch);
    mlp_k<<<GG, OUTD>>>(W1, b1, W2, b2, out);
}